// round 2
// baseline (speedup 1.0000x reference)
#include <cuda_runtime.h>
#include <cuda_bf16.h>
#include <cstdint>

// FrozenBNBEmbedding: fused blockwise-dequant + embedding gather.
// Key: BLOCK (4096) == DIM (4096) => block id of any element of row r is r.
//   out[row, d] = code[ weight[token, d] & 0xFF ] * absmax[token]
//
// Inputs (metadata order):
//   d_in[0] = input  : int32 [4, 2048]      token ids (8192 rows)
//   d_in[1] = weight : int32 [50400, 4096]  int8 codes stored as int32
//   d_in[2] = absmax : fp32  [50400]        per-block scale (block == row)
//   d_in[3] = code   : fp32  [256]          dequant LUT
// Output: fp32 [4, 2048, 4096]

#define DIM 4096
#define VEC (DIM / 4)  // 1024 int4/float4 per row

__global__ __launch_bounds__(256, 8)
void bnb_embed_kernel(const int* __restrict__ tokens,
                      const int* __restrict__ weight,
                      const float* __restrict__ absmax,
                      const float* __restrict__ code,
                      float* __restrict__ out)
{
    __shared__ float s_code[256];
    int t = threadIdx.x;
    if (t < 256) s_code[t] = code[t];
    __syncthreads();

    int row = blockIdx.x;
    int token = __ldg(&tokens[row]);
    float amax = __ldg(&absmax[token]);

    const int4* __restrict__ src = reinterpret_cast<const int4*>(weight) +
                                   (size_t)token * VEC;
    float4* __restrict__ dst = reinterpret_cast<float4*>(out) +
                               (size_t)row * VEC;

    #pragma unroll 4
    for (int i = t; i < VEC; i += 256) {
        int4 q = src[i];
        float4 v;
        v.x = s_code[q.x & 0xFF] * amax;
        v.y = s_code[q.y & 0xFF] * amax;
        v.z = s_code[q.z & 0xFF] * amax;
        v.w = s_code[q.w & 0xFF] * amax;
        dst[i] = v;
    }
}

extern "C" void kernel_launch(void* const* d_in, const int* in_sizes, int n_in,
                              void* d_out, int out_size)
{
    const int*   tokens = (const int*)d_in[0];
    const int*   weight = (const int*)d_in[1];
    const float* absmax = (const float*)d_in[2];
    const float* code   = (const float*)d_in[3];
    float*       out    = (float*)d_out;

    int n_rows = in_sizes[0];  // 8192
    bnb_embed_kernel<<<n_rows, 256>>>(tokens, weight, absmax, code, out);
}